// round 4
// baseline (speedup 1.0000x reference)
#include <cuda_runtime.h>
#include <cuda_bf16.h>
#include <cstdint>
#include <math.h>

#define PTOT     110592            // 48^3
#define NDIR     32
#define NRES     64
#define PCHUNK   192
#define NBLOCKS  (PTOT / PCHUNK)   // 576
#define NE       (4 * NDIR * NRES) // 8192 floats
#define EBPITCH  33                // padded shared pitch

// ---------------- device scratch (static; no allocations) -------------------
__device__ float         g_dirs[3 * NDIR];   // prescaled by 8*log2(e)
__device__ float         g_K[NRES];          // exp(-8*lin_r)
__device__ float         g_E[NE];            // [(b*2+c)][d][r]
__device__ int           g_tgt64;
__device__ unsigned int  g_done;
__device__ ulonglong2    g_dw[PTOT];         // .x=(dw[b0c0],dw[b0c1]) .y=(b1c0,b1c1)
__device__ float         g_eb[NDIR * PTOT];  // eb[d][p] = exp(8 * <coord_p, dir_d>)

// ---------------- asm helpers ------------------------------------------------
__device__ __forceinline__ unsigned long long pack2(float lo, float hi) {
    unsigned long long r;
    asm("mov.b64 %0, {%1, %2};" : "=l"(r) : "f"(lo), "f"(hi));
    return r;
}
__device__ __forceinline__ void unpack2(unsigned long long v, float& lo, float& hi) {
    asm("mov.b64 {%0, %1}, %2;" : "=f"(lo), "=f"(hi) : "l"(v));
}
__device__ __forceinline__ void fma2(unsigned long long& acc, unsigned long long ab,
                                     unsigned long long c) {
    asm("fma.rn.f32x2 %0, %1, %2, %0;" : "+l"(acc) : "l"(ab), "l"(c));
}
__device__ __forceinline__ unsigned long long fma2v(unsigned long long a,
                                                    unsigned long long b,
                                                    unsigned long long c) {
    unsigned long long r;
    asm("fma.rn.f32x2 %0, %1, %2, %3;" : "=l"(r) : "l"(a), "l"(b), "l"(c));
    return r;
}
__device__ __forceinline__ float rcp_approx(float x) {
    float r;
    asm("rcp.approx.f32 %0, %1;" : "=f"(r) : "f"(x));
    return r;
}
__device__ __forceinline__ float ex2_approx(float x) {
    float r;
    asm("ex2.approx.f32 %0, %1;" : "=f"(r) : "f"(x));
    return r;
}

// ---------------- threefry2x32 (JAX partitionable path) ---------------------
__device__ __forceinline__ uint32_t rotl32(uint32_t x, int d) {
    return (x << d) | (x >> (32 - d));
}
__device__ void threefry2x32(uint32_t k0, uint32_t k1, uint32_t& x0, uint32_t& x1) {
    uint32_t k2 = k0 ^ k1 ^ 0x1BD11BDAu;
    x0 += k0; x1 += k1;
#define TFR(r) { x0 += x1; x1 = rotl32(x1, r); x1 ^= x0; }
    TFR(13) TFR(15) TFR(26) TFR(6)
    x0 += k1; x1 += k2 + 1u;
    TFR(17) TFR(29) TFR(16) TFR(24)
    x0 += k2; x1 += k0 + 2u;
    TFR(13) TFR(15) TFR(26) TFR(6)
    x0 += k0; x1 += k1 + 3u;
    TFR(17) TFR(29) TFR(16) TFR(24)
    x0 += k1; x1 += k2 + 4u;
    TFR(13) TFR(15) TFR(26) TFR(6)
    x0 += k2; x1 += k0 + 5u;
#undef TFR
}

__device__ float erfinv_f32(float x) {
    float w = -log1pf(-x * x);
    float p;
    if (w < 5.0f) {
        w = w - 2.5f;
        p =            2.81022636e-08f;
        p = fmaf(p, w, 3.43273939e-07f);
        p = fmaf(p, w, -3.5233877e-06f);
        p = fmaf(p, w, -4.39150654e-06f);
        p = fmaf(p, w, 0.00021858087f);
        p = fmaf(p, w, -0.00125372503f);
        p = fmaf(p, w, -0.00417768164f);
        p = fmaf(p, w, 0.246640727f);
        p = fmaf(p, w, 1.50140941f);
    } else {
        w = sqrtf(w) - 3.0f;
        p =            -0.000200214257f;
        p = fmaf(p, w, 0.000100950558f);
        p = fmaf(p, w, 0.00134934322f);
        p = fmaf(p, w, -0.00367342844f);
        p = fmaf(p, w, 0.00573950773f);
        p = fmaf(p, w, -0.0076224613f);
        p = fmaf(p, w, 0.00943887047f);
        p = fmaf(p, w, 1.00167406f);
        p = fmaf(p, w, 2.83297682f);
    }
    return p * x;
}

// ---------------- kernel 0: init ---------------------------------------------
__global__ void init_kernel(const void* __restrict__ tgt) {
    int t = threadIdx.x;  // 128 threads

    for (int i = t; i < NE; i += 128) g_E[i] = 0.0f;
    if (t == 0) g_done = 0u;

    if (t < 32) {
        const int* ti = (const int*)tgt;
        int bad = (ti[2 * t + 1] != 0) | (ti[2 * (t + 32) + 1] != 0);
        unsigned m = __ballot_sync(0xFFFFFFFFu, bad);
        if (t == 0) g_tgt64 = (m == 0u);
    }

    __shared__ float sv[96];
    if (t < 96) {
        uint32_t x0 = 0u, x1 = (uint32_t)t;
        threefry2x32(0u, 17u, x0, x1);
        uint32_t bits = x0 ^ x1;
        float f = __uint_as_float((bits >> 9) | 0x3f800000u) - 1.0f;
        const float lo = -0.99999994f;
        float u = __fadd_rn(__fmul_rn(f, 2.0f), lo);
        u = fmaxf(u, lo);
        sv[t] = 1.41421356237f * erfinv_f32(u);
    }
    __syncthreads();
    if (t < NDIR) {
        float a = sv[t], b = sv[NDIR + t], c = sv[2 * NDIR + t];
        float n = sqrtf(a * a + b * b + c * c);
        n = fmaxf(n, 1e-12f);
        const float PRE = 8.0f * 1.4426950408889634f;  // 8*log2(e)
        g_dirs[t]            = (a / n) * PRE;
        g_dirs[NDIR + t]     = (b / n) * PRE;
        g_dirs[2 * NDIR + t] = (c / n) * PRE;
    }
    if (t < NRES) {
        double radius = 1.1 * sqrt(3.0);
        double lin = -radius + (double)t * (2.0 * radius / 63.0);
        g_K[t] = (float)exp(-8.0 * lin);
    }
}

// ---------------- kernel A: prep (dw packs + eb precompute) -----------------
__global__ __launch_bounds__(256) void prep_kernel(const float* __restrict__ pred,
                                                   const void* __restrict__ tgt) {
    __shared__ float sd[3 * NDIR];
    int tid = threadIdx.x;
    if (tid < 96) sd[tid] = g_dirs[tid];
    __syncthreads();

    int p = blockIdx.x * 256 + tid;
    int t64 = g_tgt64;

    // dw = softmax(pred) - onehot(tgt), channels 0,1 for both batches
    float dw[2][2];
#pragma unroll
    for (int b = 0; b < 2; b++) {
        float x0 = pred[(b * 3 + 0) * PTOT + p];
        float x1 = pred[(b * 3 + 1) * PTOT + p];
        float x2 = pred[(b * 3 + 2) * PTOT + p];
        float m = fmaxf(x0, fmaxf(x1, x2));
        float e0 = expf(x0 - m), e1 = expf(x1 - m), e2 = expf(x2 - m);
        float s = e0 + e1 + e2;
        int tv;
        if (t64) tv = (int)((const long long*)tgt)[b * PTOT + p];
        else     tv = ((const int*)tgt)[b * PTOT + p];
        dw[b][0] = e0 / s - (tv == 0 ? 1.0f : 0.0f);
        dw[b][1] = e1 / s - (tv == 1 ? 1.0f : 0.0f);
    }
    ulonglong2 o;
    o.x = pack2(dw[0][0], dw[0][1]);   // (b0c0, b0c1)
    o.y = pack2(dw[1][0], dw[1][1]);   // (b1c0, b1c1)
    g_dw[p] = o;

    // eb[d][p] = exp2(<coord_p, dir_d> * 8*log2e)
    int ix = p / 2304;
    int rem = p - ix * 2304;
    int iy = rem / 48;
    int iz = rem - iy * 48;
    const float CSTEP = 2.0f / 47.0f;
    float cx = fmaf((float)ix, CSTEP, -1.0f);
    float cy = fmaf((float)iy, CSTEP, -1.0f);
    float cz = fmaf((float)iz, CSTEP, -1.0f);
#pragma unroll
    for (int d = 0; d < NDIR; d++) {
        float nh = cx * sd[d];
        nh = fmaf(cy, sd[NDIR + d], nh);
        nh = fmaf(cz, sd[2 * NDIR + d], nh);
        g_eb[d * PTOT + p] = ex2_approx(nh);
    }
}

// ---------------- kernel B: main accumulation + fused final -----------------
// block = 192-p chunk; warp w owns r in [w*8, w*8+8); lane = direction
__global__ __launch_bounds__(256, 4) void main_kernel(float* __restrict__ out) {
    __shared__ float      s_eb[PCHUNK * EBPITCH];  // [i][d], padded
    __shared__ ulonglong2 s_dw[PCHUNK];
    __shared__ unsigned   s_ticket;

    int tid = threadIdx.x;
    int lane = tid & 31;
    int w = tid >> 5;
    int pbase = blockIdx.x * PCHUNK;

    for (int j = tid; j < PCHUNK; j += 256) s_dw[j] = g_dw[pbase + j];
    for (int j = tid; j < PCHUNK * NDIR; j += 256) {
        int d = j / PCHUNK;
        int i = j - d * PCHUNK;
        s_eb[i * EBPITCH + d] = g_eb[d * PTOT + pbase + i];
    }
    __syncthreads();

    // packed K pairs for this warp's 8 thresholds
    unsigned long long Kp[4];
#pragma unroll
    for (int kp = 0; kp < 4; kp++)
        Kp[kp] = pack2(g_K[w * 8 + 2 * kp], g_K[w * 8 + 2 * kp + 1]);
    const unsigned long long ONE2 = 0x3f8000003f800000ull;

    // acc0[k] = (E[b0c0], E[b0c1]) at r=w*8+k ; acc1[k] = (E[b1c0], E[b1c1])
    unsigned long long acc0[8], acc1[8];
#pragma unroll
    for (int k = 0; k < 8; k++) { acc0[k] = 0ull; acc1[k] = 0ull; }

    for (int i = 0; i < PCHUNK; i++) {
        float eb = s_eb[i * EBPITCH + lane];
        unsigned long long eb2 = pack2(eb, eb);
        ulonglong2 dw = s_dw[i];
#pragma unroll
        for (int kp = 0; kp < 4; kp++) {
            unsigned long long tp = fma2v(eb2, Kp[kp], ONE2);  // (t0,t1)
            float t0, t1;
            unpack2(tp, t0, t1);
            float s0 = rcp_approx(t0);   // sigmoid(8*(lin_r - nh))
            float s1 = rcp_approx(t1);
            unsigned long long s0d = pack2(s0, s0);
            unsigned long long s1d = pack2(s1, s1);
            fma2(acc0[2 * kp],     dw.x, s0d);
            fma2(acc1[2 * kp],     dw.y, s0d);
            fma2(acc0[2 * kp + 1], dw.x, s1d);
            fma2(acc1[2 * kp + 1], dw.y, s1d);
        }
    }

    // flush: g_E[(b*2+c)][d][r]
#pragma unroll
    for (int k = 0; k < 8; k++) {
        int r = w * 8 + k;
        float v00, v01, v10, v11;
        unpack2(acc0[k], v00, v01);
        unpack2(acc1[k], v10, v11);
        atomicAdd(&g_E[0 * 2048 + lane * NRES + r], v00);
        atomicAdd(&g_E[1 * 2048 + lane * NRES + r], v01);
        atomicAdd(&g_E[2 * 2048 + lane * NRES + r], v10);
        atomicAdd(&g_E[3 * 2048 + lane * NRES + r], v11);
    }

    // last block computes the final loss
    __threadfence();
    __syncthreads();
    if (tid == 0) s_ticket = atomicAdd(&g_done, 1u);
    __syncthreads();
    if (s_ticket != (unsigned)(NBLOCKS - 1)) return;

    float sum = 0.0f;
    for (int idx = tid; idx < 4096; idx += 256) {
        int b = idx >> 11;
        int dr = idx & 2047;
        float e0 = g_E[(b * 2 + 0) * 2048 + dr];
        float e1 = g_E[(b * 2 + 1) * 2048 + dr];
        float e2 = -(e0 + e1);                 // channel-2 by cancellation
        sum += e0 * e0 + e1 * e1 + e2 * e2;
    }
    __shared__ float red[8];
#pragma unroll
    for (int off = 16; off > 0; off >>= 1)
        sum += __shfl_down_sync(0xFFFFFFFFu, sum, off);
    if ((tid & 31) == 0) red[tid >> 5] = sum;
    __syncthreads();
    if (tid < 8) {
        float v = red[tid];
#pragma unroll
        for (int off = 4; off > 0; off >>= 1)
            v += __shfl_down_sync(0xFFu, v, off);
        if (tid == 0) out[0] = v / 12288.0f;
    }
}

// ---------------- launcher ---------------------------------------------------
extern "C" void kernel_launch(void* const* d_in, const int* in_sizes, int n_in,
                              void* d_out, int out_size) {
    const float* pred = (const float*)d_in[0];
    const void*  tgt  = d_in[1];
    float* out = (float*)d_out;
    (void)in_sizes; (void)n_in; (void)out_size;

    init_kernel<<<1, 128>>>(tgt);
    prep_kernel<<<PTOT / 256, 256>>>(pred, tgt);
    main_kernel<<<NBLOCKS, 256>>>(out);
}

// round 5
// speedup vs baseline: 1.0356x; 1.0356x over previous
#include <cuda_runtime.h>
#include <cuda_bf16.h>
#include <cstdint>
#include <math.h>

#define PTOT     110592            // 48^3
#define NDIR     32
#define NRES     64
#define PCHUNK   192
#define NCHUNKS  (PTOT / PCHUNK)   // 576
#define NBLK_B   (NCHUNKS * 2)     // 1152 (x2 r-halves)
#define NE       (4 * NDIR * NRES) // 8192 floats
#define EBPITCH  33

// ---------------- device scratch (static; no allocations) -------------------
__device__ float         g_E[NE];            // [(b*2+c)][d][r]
__device__ unsigned int  g_done;
__device__ ulonglong2    g_dw[PTOT];         // .x=(b0c0,b0c1) .y=(b1c0,b1c1)
__device__ float         g_eb[NDIR * PTOT];  // eb[d][p] = exp(8*<coord_p,dir_d>)

// ---------------- asm helpers ------------------------------------------------
__device__ __forceinline__ unsigned long long pack2(float lo, float hi) {
    unsigned long long r;
    asm("mov.b64 %0, {%1, %2};" : "=l"(r) : "f"(lo), "f"(hi));
    return r;
}
__device__ __forceinline__ void unpack2(unsigned long long v, float& lo, float& hi) {
    asm("mov.b64 {%0, %1}, %2;" : "=f"(lo), "=f"(hi) : "l"(v));
}
__device__ __forceinline__ void fma2(unsigned long long& acc, unsigned long long ab,
                                     unsigned long long c) {
    asm("fma.rn.f32x2 %0, %1, %2, %0;" : "+l"(acc) : "l"(ab), "l"(c));
}
__device__ __forceinline__ float rcp_approx(float x) {
    float r;
    asm("rcp.approx.f32 %0, %1;" : "=f"(r) : "f"(x));
    return r;
}
__device__ __forceinline__ float ex2_approx(float x) {
    float r;
    asm("ex2.approx.f32 %0, %1;" : "=f"(r) : "f"(x));
    return r;
}

// ---------------- threefry2x32 (JAX partitionable path) ---------------------
__device__ __forceinline__ uint32_t rotl32(uint32_t x, int d) {
    return (x << d) | (x >> (32 - d));
}
__device__ void threefry2x32(uint32_t k0, uint32_t k1, uint32_t& x0, uint32_t& x1) {
    uint32_t k2 = k0 ^ k1 ^ 0x1BD11BDAu;
    x0 += k0; x1 += k1;
#define TFR(r) { x0 += x1; x1 = rotl32(x1, r); x1 ^= x0; }
    TFR(13) TFR(15) TFR(26) TFR(6)
    x0 += k1; x1 += k2 + 1u;
    TFR(17) TFR(29) TFR(16) TFR(24)
    x0 += k2; x1 += k0 + 2u;
    TFR(13) TFR(15) TFR(26) TFR(6)
    x0 += k0; x1 += k1 + 3u;
    TFR(17) TFR(29) TFR(16) TFR(24)
    x0 += k1; x1 += k2 + 4u;
    TFR(13) TFR(15) TFR(26) TFR(6)
    x0 += k2; x1 += k0 + 5u;
#undef TFR
}

__device__ float erfinv_f32(float x) {
    float w = -log1pf(-x * x);
    float p;
    if (w < 5.0f) {
        w = w - 2.5f;
        p =            2.81022636e-08f;
        p = fmaf(p, w, 3.43273939e-07f);
        p = fmaf(p, w, -3.5233877e-06f);
        p = fmaf(p, w, -4.39150654e-06f);
        p = fmaf(p, w, 0.00021858087f);
        p = fmaf(p, w, -0.00125372503f);
        p = fmaf(p, w, -0.00417768164f);
        p = fmaf(p, w, 0.246640727f);
        p = fmaf(p, w, 1.50140941f);
    } else {
        w = sqrtf(w) - 3.0f;
        p =            -0.000200214257f;
        p = fmaf(p, w, 0.000100950558f);
        p = fmaf(p, w, 0.00134934322f);
        p = fmaf(p, w, -0.00367342844f);
        p = fmaf(p, w, 0.00573950773f);
        p = fmaf(p, w, -0.0076224613f);
        p = fmaf(p, w, 0.00943887047f);
        p = fmaf(p, w, 1.00167406f);
        p = fmaf(p, w, 2.83297682f);
    }
    return p * x;
}

// ---------------- kernel A: init (block 0) + prep + eb precompute -----------
__global__ __launch_bounds__(256) void kernelA(const float* __restrict__ pred,
                                               const void* __restrict__ tgt) {
    __shared__ float sv[96];
    __shared__ float sd[96];
    __shared__ int   s_t64;
    int tid = threadIdx.x;

    if (tid == 0) {
        // int64 targets (values 0..2, little-endian): odd 32-bit words all 0
        const int* ti = (const int*)tgt;
        int all0 = 1;
        for (int q = 0; q < 64; q++)
            if (ti[2 * q + 1] != 0) { all0 = 0; break; }
        s_t64 = all0;
    }
    if (tid < 96) {
        uint32_t x0 = 0u, x1 = (uint32_t)tid;
        threefry2x32(0u, 17u, x0, x1);
        uint32_t bits = x0 ^ x1;
        float f = __uint_as_float((bits >> 9) | 0x3f800000u) - 1.0f;
        const float lo = -0.99999994f;
        float u = __fadd_rn(__fmul_rn(f, 2.0f), lo);
        u = fmaxf(u, lo);
        sv[tid] = 1.41421356237f * erfinv_f32(u);
    }
    __syncthreads();
    if (tid < NDIR) {
        float a = sv[tid], b = sv[NDIR + tid], c = sv[2 * NDIR + tid];
        float n = sqrtf(a * a + b * b + c * c);
        n = fmaxf(n, 1e-12f);
        const float PRE = 8.0f * 1.4426950408889634f;  // 8*log2(e)
        sd[tid]            = (a / n) * PRE;
        sd[NDIR + tid]     = (b / n) * PRE;
        sd[2 * NDIR + tid] = (c / n) * PRE;
    }
    if (blockIdx.x == 0) {
        for (int i = tid; i < NE; i += 256) g_E[i] = 0.0f;
        if (tid == 0) g_done = 0u;
    }
    __syncthreads();
    int t64 = s_t64;
    int p = blockIdx.x * 256 + tid;

    // dw = softmax(pred) - onehot(tgt), channels 0,1, both batches
    float dw[2][2];
#pragma unroll
    for (int b = 0; b < 2; b++) {
        float x0 = pred[(b * 3 + 0) * PTOT + p];
        float x1 = pred[(b * 3 + 1) * PTOT + p];
        float x2 = pred[(b * 3 + 2) * PTOT + p];
        float m = fmaxf(x0, fmaxf(x1, x2));
        float e0 = expf(x0 - m), e1 = expf(x1 - m), e2 = expf(x2 - m);
        float s = e0 + e1 + e2;
        int tv;
        if (t64) tv = (int)((const long long*)tgt)[b * PTOT + p];
        else     tv = ((const int*)tgt)[b * PTOT + p];
        dw[b][0] = e0 / s - (tv == 0 ? 1.0f : 0.0f);
        dw[b][1] = e1 / s - (tv == 1 ? 1.0f : 0.0f);
    }
    ulonglong2 o;
    o.x = pack2(dw[0][0], dw[0][1]);
    o.y = pack2(dw[1][0], dw[1][1]);
    g_dw[p] = o;

    // eb[d][p] = exp2(<coord_p, dir_d> * 8*log2e)
    int ix = p / 2304;
    int rem = p - ix * 2304;
    int iy = rem / 48;
    int iz = rem - iy * 48;
    const float CSTEP = 2.0f / 47.0f;
    float cx = fmaf((float)ix, CSTEP, -1.0f);
    float cy = fmaf((float)iy, CSTEP, -1.0f);
    float cz = fmaf((float)iz, CSTEP, -1.0f);
#pragma unroll
    for (int d = 0; d < NDIR; d++) {
        float nh = cx * sd[d];
        nh = fmaf(cy, sd[NDIR + d], nh);
        nh = fmaf(cz, sd[2 * NDIR + d], nh);
        g_eb[d * PTOT + p] = ex2_approx(nh);
    }
}

// ---------------- kernel B: main accumulation + fused final -----------------
// grid = 576 p-chunks x 2 r-halves; warp w owns 4 thresholds; lane = direction
__global__ __launch_bounds__(256, 5) void kernelB(float* __restrict__ out) {
    __shared__ float      s_eb[PCHUNK * EBPITCH];  // [i][d], padded
    __shared__ ulonglong2 s_dw[PCHUNK];
    __shared__ unsigned   s_ticket;

    int tid = threadIdx.x;
    int lane = tid & 31;
    int w = tid >> 5;
    int chunk = blockIdx.x >> 1;
    int rbase = (blockIdx.x & 1) * 32 + w * 4;  // this warp's 4 thresholds
    int pbase = chunk * PCHUNK;

    for (int j = tid; j < PCHUNK; j += 256) s_dw[j] = g_dw[pbase + j];
    for (int j = tid; j < PCHUNK * NDIR; j += 256) {
        int d = j / PCHUNK;
        int i = j - d * PCHUNK;
        s_eb[i * EBPITCH + d] = g_eb[d * PTOT + pbase + i];
    }

    // K[k] = exp(-8*lin_r), computed per warp (double for linspace fidelity)
    float K[4];
    {
        double radius = 1.1 * sqrt(3.0);
        double step = 2.0 * radius / 63.0;
#pragma unroll
        for (int k = 0; k < 4; k++) {
            double lin = -radius + (double)(rbase + k) * step;
            K[k] = (float)exp(-8.0 * lin);
        }
    }
    __syncthreads();

    // acc0[k] = (E[b0c0],E[b0c1]) ; acc1[k] = (E[b1c0],E[b1c1]) at r=rbase+k
    unsigned long long acc0[4], acc1[4];
#pragma unroll
    for (int k = 0; k < 4; k++) { acc0[k] = 0ull; acc1[k] = 0ull; }

    for (int i = 0; i < PCHUNK; i++) {
        float eb = s_eb[i * EBPITCH + lane];
        ulonglong2 dw = s_dw[i];
#pragma unroll
        for (int k = 0; k < 4; k++) {
            float t = fmaf(eb, K[k], 1.0f);
            float s = rcp_approx(t);         // sigmoid(8*(lin_r - nh))
            unsigned long long sd = pack2(s, s);
            fma2(acc0[k], dw.x, sd);
            fma2(acc1[k], dw.y, sd);
        }
    }

    // flush: g_E[(b*2+c)][d][r]
#pragma unroll
    for (int k = 0; k < 4; k++) {
        int r = rbase + k;
        float v00, v01, v10, v11;
        unpack2(acc0[k], v00, v01);
        unpack2(acc1[k], v10, v11);
        atomicAdd(&g_E[0 * 2048 + lane * NRES + r], v00);
        atomicAdd(&g_E[1 * 2048 + lane * NRES + r], v01);
        atomicAdd(&g_E[2 * 2048 + lane * NRES + r], v10);
        atomicAdd(&g_E[3 * 2048 + lane * NRES + r], v11);
    }

    // last block computes the final loss
    __threadfence();
    __syncthreads();
    if (tid == 0) s_ticket = atomicAdd(&g_done, 1u);
    __syncthreads();
    if (s_ticket != (unsigned)(NBLK_B - 1)) return;

    float sum = 0.0f;
    for (int idx = tid; idx < 4096; idx += 256) {
        int b = idx >> 11;
        int dr = idx & 2047;
        float e0 = g_E[(b * 2 + 0) * 2048 + dr];
        float e1 = g_E[(b * 2 + 1) * 2048 + dr];
        float e2 = -(e0 + e1);                 // channel-2 by cancellation
        sum += e0 * e0 + e1 * e1 + e2 * e2;
    }
    __shared__ float red[8];
#pragma unroll
    for (int off = 16; off > 0; off >>= 1)
        sum += __shfl_down_sync(0xFFFFFFFFu, sum, off);
    if ((tid & 31) == 0) red[tid >> 5] = sum;
    __syncthreads();
    if (tid < 8) {
        float v = red[tid];
#pragma unroll
        for (int off = 4; off > 0; off >>= 1)
            v += __shfl_down_sync(0xFFu, v, off);
        if (tid == 0) out[0] = v / 12288.0f;
    }
}

// ---------------- launcher ---------------------------------------------------
extern "C" void kernel_launch(void* const* d_in, const int* in_sizes, int n_in,
                              void* d_out, int out_size) {
    const float* pred = (const float*)d_in[0];
    const void*  tgt  = d_in[1];
    float* out = (float*)d_out;
    (void)in_sizes; (void)n_in; (void)out_size;

    kernelA<<<PTOT / 256, 256>>>(pred, tgt);
    kernelB<<<NBLK_B, 256>>>(out);
}